// round 1
// baseline (speedup 1.0000x reference)
#include <cuda_runtime.h>
#include <math.h>

#define BATCH 4
#define SEQ   2048
#define HID   256
#define NTOK  (BATCH*SEQ)   // 8192
#define NHEAD 8
#define DPH   32
#define WINSZ 64
#define NWIN  32

// ---------------- scratch (no allocs allowed) ----------------
__device__ float g_q[NTOK*HID];
__device__ float g_k[NTOK*HID];
__device__ float g_v[NTOK*HID];
__device__ float g_pe1[NTOK*HID];
__device__ float g_pe[NTOK*HID];
__device__ float g_ctx[NTOK*HID];

__device__ __forceinline__ float gelu_exact(float x) {
    return 0.5f * x * (1.0f + erff(x * 0.70710678118654752f));
}

// ---------------- generic GEMM: C = act(scale*(A@W + bias)) ----------------
// A: (M,256) row-major, W: (256,256) row-major, M = 8192.
// 64x64 tile per block, 256 threads, 4x4 per thread, BK=32.
__global__ __launch_bounds__(256) void gemm_k(
    const float* __restrict__ A, const float* __restrict__ W,
    const float* __restrict__ bias, float* __restrict__ C,
    float scale, int act)
{
    __shared__ float As[32][68];   // transposed A tile, padded (16B aligned rows)
    __shared__ float Bs[32][64];

    const int tx = threadIdx.x & 15;
    const int ty = threadIdx.x >> 4;
    const int m0 = blockIdx.x * 64;
    const int n0 = blockIdx.y * 64;

    float acc[4][4];
#pragma unroll
    for (int i = 0; i < 4; i++)
#pragma unroll
        for (int j = 0; j < 4; j++) acc[i][j] = 0.f;

    const int fA = threadIdx.x & 7;   // float4 column in A tile
    const int rA = threadIdx.x >> 3;  // row 0..31 (and +32)

    for (int kk = 0; kk < 256; kk += 32) {
        // load A tile (64 x 32), store transposed
#pragma unroll
        for (int rr = 0; rr < 2; rr++) {
            int row = rA + rr * 32;
            float4 va = *(const float4*)(A + (size_t)(m0 + row) * 256 + kk + fA * 4);
            As[fA * 4 + 0][row] = va.x;
            As[fA * 4 + 1][row] = va.y;
            As[fA * 4 + 2][row] = va.z;
            As[fA * 4 + 3][row] = va.w;
        }
        // load B tile (32 x 64)
#pragma unroll
        for (int rr = 0; rr < 2; rr++) {
            int kx = ty + rr * 16;
            *(float4*)(&Bs[kx][tx * 4]) =
                *(const float4*)(W + (size_t)(kk + kx) * 256 + n0 + tx * 4);
        }
        __syncthreads();

#pragma unroll
        for (int k = 0; k < 32; k++) {
            float4 a4 = *(const float4*)(&As[k][ty * 4]);
            float4 b4 = *(const float4*)(&Bs[k][tx * 4]);
            float a[4] = {a4.x, a4.y, a4.z, a4.w};
            float b[4] = {b4.x, b4.y, b4.z, b4.w};
#pragma unroll
            for (int i = 0; i < 4; i++)
#pragma unroll
                for (int j = 0; j < 4; j++) acc[i][j] += a[i] * b[j];
        }
        __syncthreads();
    }

#pragma unroll
    for (int i = 0; i < 4; i++) {
        int m = m0 + ty * 4 + i;
#pragma unroll
        for (int j = 0; j < 4; j++) {
            int n = n0 + tx * 4 + j;
            float v = (acc[i][j] + bias[n]) * scale;
            if (act) v = gelu_exact(v);
            C[(size_t)m * 256 + n] = v;
        }
    }
}

// ---------------- pos-MLP stage 1: Linear(2,256) -> LN -> GELU ----------------
__global__ __launch_bounds__(256) void pos1_k(
    const float* __restrict__ p, const float* __restrict__ p1w,
    const float* __restrict__ p1b, const float* __restrict__ lng,
    const float* __restrict__ lnb, float* __restrict__ out)
{
    const int tok = blockIdx.x;
    const int n = threadIdx.x;
    const float p0 = p[tok * 2 + 0];
    const float p1v = p[tok * 2 + 1];
    float h = p0 * p1w[n] + p1v * p1w[256 + n] + p1b[n];

    __shared__ float red[8];
    __shared__ float s_mu, s_var;

    float v = h;
#pragma unroll
    for (int o = 16; o; o >>= 1) v += __shfl_xor_sync(0xffffffffu, v, o);
    if ((n & 31) == 0) red[n >> 5] = v;
    __syncthreads();
    if (n == 0) {
        float s = 0.f;
#pragma unroll
        for (int i = 0; i < 8; i++) s += red[i];
        s_mu = s * (1.f / 256.f);
    }
    __syncthreads();
    const float mu = s_mu;
    float dv = h - mu;
    v = dv * dv;
#pragma unroll
    for (int o = 16; o; o >>= 1) v += __shfl_xor_sync(0xffffffffu, v, o);
    if ((n & 31) == 0) red[n >> 5] = v;
    __syncthreads();
    if (n == 0) {
        float s = 0.f;
#pragma unroll
        for (int i = 0; i < 8; i++) s += red[i];
        s_var = s * (1.f / 256.f);
    }
    __syncthreads();
    float y = (h - mu) * rsqrtf(s_var + 1e-6f) * lng[n] + lnb[n];
    out[(size_t)tok * 256 + n] = gelu_exact(y);
}

// ---------------- windowed attention ----------------
// One block per (window, head, batch). 256 threads.
// S[i,j] = q_i·(k_j - pe_j) + (c·k_j - d·pe_j) + (q_i + d)·pe_i
__global__ __launch_bounds__(256) void attn_k(
    const float* __restrict__ q, const float* __restrict__ k,
    const float* __restrict__ v, const float* __restrict__ pe,
    const float* __restrict__ cvec, const float* __restrict__ dvec,
    float* __restrict__ ctx)
{
    const int w = blockIdx.x, h = blockIdx.y, b = blockIdx.z;

    __shared__ float sq[64][36];
    __shared__ float skw[64][36];   // k - pe
    __shared__ float sv[64][36];
    __shared__ float sbias[64];     // c·k_j - d·pe_j
    __shared__ float su[64];        // (q_i + d)·pe_i
    __shared__ float P[64][65];

    const int t = threadIdx.x;
    const int tok = t >> 2;
    const int l = t & 3;
    const int dl = l * 8;

    // shifted -> original token index (bijection)
    const int s = w * 64 + tok;
    const int o = s >> 4, r = s & 15;
    const int ic = ((o & 63) << 1) + (o >> 6);
    const int orig = ic * 16 + r;
    const size_t base = ((size_t)(b * SEQ + orig)) * 256 + h * 32 + dl;

    const float* cp = cvec + h * 32 + dl;
    const float* dp = dvec + h * 32 + dl;

    float bias_p = 0.f, u_p = 0.f;
#pragma unroll
    for (int i = 0; i < 8; i += 4) {
        float4 xq = *(const float4*)(q + base + i);
        float4 xk = *(const float4*)(k + base + i);
        float4 xv = *(const float4*)(v + base + i);
        float4 xp = *(const float4*)(pe + base + i);
        float4 xc = *(const float4*)(cp + i);
        float4 xd = *(const float4*)(dp + i);
        *(float4*)(&sq[tok][dl + i]) = xq;
        *(float4*)(&sv[tok][dl + i]) = xv;
        float4 kw = make_float4(xk.x - xp.x, xk.y - xp.y, xk.z - xp.z, xk.w - xp.w);
        *(float4*)(&skw[tok][dl + i]) = kw;
        bias_p += xc.x * xk.x + xc.y * xk.y + xc.z * xk.z + xc.w * xk.w;
        bias_p -= xd.x * xp.x + xd.y * xp.y + xd.z * xp.z + xd.w * xp.w;
        u_p += (xq.x + xd.x) * xp.x + (xq.y + xd.y) * xp.y +
               (xq.z + xd.z) * xp.z + (xq.w + xd.w) * xp.w;
    }
    // reduce across the 4 lanes of this token's quad
    bias_p += __shfl_xor_sync(0xffffffffu, bias_p, 1);
    bias_p += __shfl_xor_sync(0xffffffffu, bias_p, 2);
    u_p += __shfl_xor_sync(0xffffffffu, u_p, 1);
    u_p += __shfl_xor_sync(0xffffffffu, u_p, 2);
    if (l == 0) { sbias[tok] = bias_p; su[tok] = u_p; }
    __syncthreads();

    // ---- scores: row = tok, this thread handles columns j = l + 4*jj ----
    const int row = tok;
    float qrow[32];
#pragma unroll
    for (int d = 0; d < 32; d += 4) {
        float4 x = *(const float4*)(&sq[row][d]);
        qrow[d] = x.x; qrow[d + 1] = x.y; qrow[d + 2] = x.z; qrow[d + 3] = x.w;
    }
    const float urow = su[row];
    float sc[16];
    float smax = -1e30f;
#pragma unroll
    for (int jj = 0; jj < 16; jj++) {
        int j = l + (jj << 2);
        float sv2 = urow + sbias[j];
#pragma unroll
        for (int d = 0; d < 32; d += 4) {
            float4 kv = *(const float4*)(&skw[j][d]);
            sv2 += qrow[d] * kv.x + qrow[d + 1] * kv.y +
                   qrow[d + 2] * kv.z + qrow[d + 3] * kv.w;
        }
        sc[jj] = sv2;
        smax = fmaxf(smax, sv2);
    }
    smax = fmaxf(smax, __shfl_xor_sync(0xffffffffu, smax, 1));
    smax = fmaxf(smax, __shfl_xor_sync(0xffffffffu, smax, 2));
    float ssum = 0.f;
#pragma unroll
    for (int jj = 0; jj < 16; jj++) {
        sc[jj] = __expf(sc[jj] - smax);
        ssum += sc[jj];
    }
    ssum += __shfl_xor_sync(0xffffffffu, ssum, 1);
    ssum += __shfl_xor_sync(0xffffffffu, ssum, 2);
    const float inv = 1.f / ssum;
#pragma unroll
    for (int jj = 0; jj < 16; jj++) P[row][l + (jj << 2)] = sc[jj] * inv;
    __syncthreads();

    // ---- O = P @ v : this thread produces O[row][dl .. dl+7] ----
    float oa0 = 0.f, oa1 = 0.f, oa2 = 0.f, oa3 = 0.f;
    float oa4 = 0.f, oa5 = 0.f, oa6 = 0.f, oa7 = 0.f;
#pragma unroll
    for (int j = 0; j < 64; j++) {
        float pv = P[row][j];
        float4 v0 = *(const float4*)(&sv[j][dl]);
        float4 v1 = *(const float4*)(&sv[j][dl + 4]);
        oa0 += pv * v0.x; oa1 += pv * v0.y; oa2 += pv * v0.z; oa3 += pv * v0.w;
        oa4 += pv * v1.x; oa5 += pv * v1.y; oa6 += pv * v1.z; oa7 += pv * v1.w;
    }
    // scatter back (inverse shift-perm == same index map)
    *(float4*)(ctx + base)     = make_float4(oa0, oa1, oa2, oa3);
    *(float4*)(ctx + base + 4) = make_float4(oa4, oa5, oa6, oa7);
}

// ---------------- launch ----------------
extern "C" void kernel_launch(void* const* d_in, const int* in_sizes, int n_in,
                              void* d_out, int out_size)
{
    const float* inputs = (const float*)d_in[0];
    const float* p      = (const float*)d_in[1];
    const float* wq     = (const float*)d_in[2];
    const float* bq     = (const float*)d_in[3];
    const float* wk     = (const float*)d_in[4];
    const float* bk     = (const float*)d_in[5];
    const float* wv     = (const float*)d_in[6];
    const float* bv     = (const float*)d_in[7];
    const float* wo     = (const float*)d_in[8];
    const float* bo     = (const float*)d_in[9];
    const float* p1w    = (const float*)d_in[10];
    const float* p1b    = (const float*)d_in[11];
    const float* p2w    = (const float*)d_in[12];
    const float* p2b    = (const float*)d_in[13];
    const float* lng    = (const float*)d_in[14];
    const float* lnb    = (const float*)d_in[15];
    const float* cv     = (const float*)d_in[16];
    const float* dv     = (const float*)d_in[17];
    float* out = (float*)d_out;

    float *q, *k, *v, *pe1, *pe, *ctx;
    cudaGetSymbolAddress((void**)&q,   g_q);
    cudaGetSymbolAddress((void**)&k,   g_k);
    cudaGetSymbolAddress((void**)&v,   g_v);
    cudaGetSymbolAddress((void**)&pe1, g_pe1);
    cudaGetSymbolAddress((void**)&pe,  g_pe);
    cudaGetSymbolAddress((void**)&ctx, g_ctx);

    const dim3 gg(NTOK / 64, HID / 64, 1);
    const float qscale = 0.17677669529663689f;  // 1/sqrt(32)

    gemm_k<<<gg, 256>>>(inputs, wq, bq, q, qscale, 0);
    gemm_k<<<gg, 256>>>(inputs, wk, bk, k, 1.f, 0);
    gemm_k<<<gg, 256>>>(inputs, wv, bv, v, 1.f, 0);
    pos1_k<<<NTOK, 256>>>(p, p1w, p1b, lng, lnb, pe1);
    gemm_k<<<gg, 256>>>(pe1, p2w, p2b, pe, 1.f, 1);
    attn_k<<<dim3(NWIN, NHEAD, BATCH), 256>>>(q, k, v, pe, cv, dv, ctx);
    gemm_k<<<gg, 256>>>(ctx, wo, bo, out, 1.f, 0);
}

// round 2
// speedup vs baseline: 1.3266x; 1.3266x over previous
#include <cuda_runtime.h>
#include <math.h>
#include <stdint.h>

#define BATCH 4
#define SEQ   2048
#define HID   256
#define NTOK  (BATCH*SEQ)   // 8192
#define NHEAD 8
#define DPH   32
#define WINSZ 64
#define NWIN  32

// ---------------- scratch (no allocs allowed) ----------------
__device__ float g_q[NTOK*HID];
__device__ float g_k[NTOK*HID];
__device__ float g_v[NTOK*HID];
__device__ float g_pe1[NTOK*HID];
__device__ float g_pe[NTOK*HID];
__device__ float g_ctx[NTOK*HID];

__device__ __forceinline__ float gelu_exact(float x) {
    return 0.5f * x * (1.0f + erff(x * 0.70710678118654752f));
}

__device__ __forceinline__ float tf32r(float x) {
    uint32_t r;
    asm("cvt.rna.tf32.f32 %0, %1;" : "=r"(r) : "f"(x));
    return __uint_as_float(r);
}

__device__ __forceinline__ void mma_tf32(float* d, const uint32_t* a, const uint32_t* b) {
    asm volatile(
        "mma.sync.aligned.m16n8k8.row.col.f32.tf32.tf32.f32 "
        "{%0,%1,%2,%3}, {%4,%5,%6,%7}, {%8,%9}, {%0,%1,%2,%3};\n"
        : "+f"(d[0]), "+f"(d[1]), "+f"(d[2]), "+f"(d[3])
        : "r"(a[0]), "r"(a[1]), "r"(a[2]), "r"(a[3]), "r"(b[0]), "r"(b[1]));
}

// ---------------- tensor-core GEMM: C = act(scale*(A@W + bias)) ----------------
// A: (8192,256) rm, W: (256,256) rm. 3xTF32 compensated (near-fp32 accuracy).
// BM=128, BN=64, BK=16. 8 warps; warp tile 32x32 (2 x m16, 4 x n8).
#define BM 128
#define BN 64
#define BK 16

__global__ __launch_bounds__(256) void gemm_tc(
    const float* __restrict__ A, const float* __restrict__ W,
    const float* __restrict__ bias, float* __restrict__ C,
    float scale, int act)
{
    __shared__ float Ah[BM][20];   // [m][k], pad->20: conflict-free frag loads+stores
    __shared__ float Al[BM][20];
    __shared__ float Bh[BK][72];   // [k][n], pad->72: conflict-free frag loads+stores
    __shared__ float Bl[BK][72];

    const int tid  = threadIdx.x;
    const int wid  = tid >> 5;
    const int lane = tid & 31;
    const int g = lane >> 2;        // group id (0..7)
    const int q = lane & 3;         // thread in group
    const int wm = (wid & 3) * 32;  // warp m offset within block tile
    const int wn = (wid >> 2) * 32; // warp n offset
    const int m0 = blockIdx.x * BM;
    const int n0 = blockIdx.y * BN;

    float acc[2][4][4];
#pragma unroll
    for (int mt = 0; mt < 2; mt++)
#pragma unroll
        for (int nt = 0; nt < 4; nt++)
#pragma unroll
            for (int i = 0; i < 4; i++) acc[mt][nt][i] = 0.f;

    for (int kk = 0; kk < 256; kk += BK) {
        // ---- stage A tile (128x16) hi/lo, 2 float4 per thread ----
#pragma unroll
        for (int i = 0; i < 2; i++) {
            int f4 = i * 256 + tid;
            int row = f4 >> 2;
            int c4  = (f4 & 3) * 4;
            float4 va = *(const float4*)(A + (size_t)(m0 + row) * 256 + kk + c4);
            float4 hi, lo;
            hi.x = tf32r(va.x); lo.x = tf32r(va.x - hi.x);
            hi.y = tf32r(va.y); lo.y = tf32r(va.y - hi.y);
            hi.z = tf32r(va.z); lo.z = tf32r(va.z - hi.z);
            hi.w = tf32r(va.w); lo.w = tf32r(va.w - hi.w);
            *(float4*)(&Ah[row][c4]) = hi;
            *(float4*)(&Al[row][c4]) = lo;
        }
        // ---- stage B tile (16x64) hi/lo, 1 float4 per thread ----
        {
            int row = tid >> 4;
            int c4  = (tid & 15) * 4;
            float4 vb = *(const float4*)(W + (size_t)(kk + row) * 256 + n0 + c4);
            float4 hi, lo;
            hi.x = tf32r(vb.x); lo.x = tf32r(vb.x - hi.x);
            hi.y = tf32r(vb.y); lo.y = tf32r(vb.y - hi.y);
            hi.z = tf32r(vb.z); lo.z = tf32r(vb.z - hi.z);
            hi.w = tf32r(vb.w); lo.w = tf32r(vb.w - hi.w);
            *(float4*)(&Bh[row][c4]) = hi;
            *(float4*)(&Bl[row][c4]) = lo;
        }
        __syncthreads();

#pragma unroll
        for (int ks = 0; ks < BK; ks += 8) {
            uint32_t afh[2][4], afl[2][4], bfh[4][2], bfl[4][2];
#pragma unroll
            for (int mt = 0; mt < 2; mt++) {
                int r = wm + mt * 16 + g;
                afh[mt][0] = __float_as_uint(Ah[r    ][ks + q    ]);
                afh[mt][1] = __float_as_uint(Ah[r + 8][ks + q    ]);
                afh[mt][2] = __float_as_uint(Ah[r    ][ks + q + 4]);
                afh[mt][3] = __float_as_uint(Ah[r + 8][ks + q + 4]);
                afl[mt][0] = __float_as_uint(Al[r    ][ks + q    ]);
                afl[mt][1] = __float_as_uint(Al[r + 8][ks + q    ]);
                afl[mt][2] = __float_as_uint(Al[r    ][ks + q + 4]);
                afl[mt][3] = __float_as_uint(Al[r + 8][ks + q + 4]);
            }
#pragma unroll
            for (int nt = 0; nt < 4; nt++) {
                int n = wn + nt * 8 + g;
                bfh[nt][0] = __float_as_uint(Bh[ks + q    ][n]);
                bfh[nt][1] = __float_as_uint(Bh[ks + q + 4][n]);
                bfl[nt][0] = __float_as_uint(Bl[ks + q    ][n]);
                bfl[nt][1] = __float_as_uint(Bl[ks + q + 4][n]);
            }
#pragma unroll
            for (int mt = 0; mt < 2; mt++)
#pragma unroll
                for (int nt = 0; nt < 4; nt++) {
                    mma_tf32(acc[mt][nt], afh[mt], bfh[nt]);
                    mma_tf32(acc[mt][nt], afh[mt], bfl[nt]);
                    mma_tf32(acc[mt][nt], afl[mt], bfh[nt]);
                }
        }
        __syncthreads();
    }

    // ---- epilogue ----
#pragma unroll
    for (int mt = 0; mt < 2; mt++) {
        int r0 = m0 + wm + mt * 16 + g;
#pragma unroll
        for (int nt = 0; nt < 4; nt++) {
            int cn = n0 + wn + nt * 8 + 2 * q;
            float2 b2 = *(const float2*)(bias + cn);
            float v0 = (acc[mt][nt][0] + b2.x) * scale;
            float v1 = (acc[mt][nt][1] + b2.y) * scale;
            float v2 = (acc[mt][nt][2] + b2.x) * scale;
            float v3 = (acc[mt][nt][3] + b2.y) * scale;
            if (act) {
                v0 = gelu_exact(v0); v1 = gelu_exact(v1);
                v2 = gelu_exact(v2); v3 = gelu_exact(v3);
            }
            *(float2*)(C + (size_t)r0 * 256 + cn)       = make_float2(v0, v1);
            *(float2*)(C + (size_t)(r0 + 8) * 256 + cn) = make_float2(v2, v3);
        }
    }
}

// ---------------- pos-MLP stage 1: warp-per-token, shfl-only ----------------
__global__ __launch_bounds__(256) void pos1_k(
    const float* __restrict__ p, const float* __restrict__ p1w,
    const float* __restrict__ p1b, const float* __restrict__ lng,
    const float* __restrict__ lnb, float* __restrict__ out)
{
    const int warp = threadIdx.x >> 5;
    const int lane = threadIdx.x & 31;
    const int tok = blockIdx.x * 8 + warp;
    const float p0  = p[tok * 2 + 0];
    const float p1v = p[tok * 2 + 1];

    float h[8];
    float s = 0.f;
#pragma unroll
    for (int j = 0; j < 8; j++) {
        int n = lane + 32 * j;
        h[j] = p0 * p1w[n] + p1v * p1w[256 + n] + p1b[n];
        s += h[j];
    }
#pragma unroll
    for (int o = 16; o; o >>= 1) s += __shfl_xor_sync(0xffffffffu, s, o);
    const float mu = s * (1.f / 256.f);

    float vs = 0.f;
#pragma unroll
    for (int j = 0; j < 8; j++) {
        float d = h[j] - mu;
        vs += d * d;
    }
#pragma unroll
    for (int o = 16; o; o >>= 1) vs += __shfl_xor_sync(0xffffffffu, vs, o);
    const float rstd = rsqrtf(vs * (1.f / 256.f) + 1e-6f);

#pragma unroll
    for (int j = 0; j < 8; j++) {
        int n = lane + 32 * j;
        float y = (h[j] - mu) * rstd * lng[n] + lnb[n];
        out[(size_t)tok * 256 + n] = gelu_exact(y);
    }
}

// ---------------- windowed attention (unchanged from R1) ----------------
// S[i,j] = q_i·(k_j - pe_j) + (c·k_j - d·pe_j) + (q_i + d)·pe_i
__global__ __launch_bounds__(256) void attn_k(
    const float* __restrict__ q, const float* __restrict__ k,
    const float* __restrict__ v, const float* __restrict__ pe,
    const float* __restrict__ cvec, const float* __restrict__ dvec,
    float* __restrict__ ctx)
{
    const int w = blockIdx.x, h = blockIdx.y, b = blockIdx.z;

    __shared__ float sq[64][36];
    __shared__ float skw[64][36];
    __shared__ float sv[64][36];
    __shared__ float sbias[64];
    __shared__ float su[64];
    __shared__ float P[64][65];

    const int t = threadIdx.x;
    const int tok = t >> 2;
    const int l = t & 3;
    const int dl = l * 8;

    const int s = w * 64 + tok;
    const int o = s >> 4, r = s & 15;
    const int ic = ((o & 63) << 1) + (o >> 6);
    const int orig = ic * 16 + r;
    const size_t base = ((size_t)(b * SEQ + orig)) * 256 + h * 32 + dl;

    const float* cp = cvec + h * 32 + dl;
    const float* dp = dvec + h * 32 + dl;

    float bias_p = 0.f, u_p = 0.f;
#pragma unroll
    for (int i = 0; i < 8; i += 4) {
        float4 xq = *(const float4*)(q + base + i);
        float4 xk = *(const float4*)(k + base + i);
        float4 xv = *(const float4*)(v + base + i);
        float4 xp = *(const float4*)(pe + base + i);
        float4 xc = *(const float4*)(cp + i);
        float4 xd = *(const float4*)(dp + i);
        *(float4*)(&sq[tok][dl + i]) = xq;
        *(float4*)(&sv[tok][dl + i]) = xv;
        float4 kw = make_float4(xk.x - xp.x, xk.y - xp.y, xk.z - xp.z, xk.w - xp.w);
        *(float4*)(&skw[tok][dl + i]) = kw;
        bias_p += xc.x * xk.x + xc.y * xk.y + xc.z * xk.z + xc.w * xk.w;
        bias_p -= xd.x * xp.x + xd.y * xp.y + xd.z * xp.z + xd.w * xp.w;
        u_p += (xq.x + xd.x) * xp.x + (xq.y + xd.y) * xp.y +
               (xq.z + xd.z) * xp.z + (xq.w + xd.w) * xp.w;
    }
    bias_p += __shfl_xor_sync(0xffffffffu, bias_p, 1);
    bias_p += __shfl_xor_sync(0xffffffffu, bias_p, 2);
    u_p += __shfl_xor_sync(0xffffffffu, u_p, 1);
    u_p += __shfl_xor_sync(0xffffffffu, u_p, 2);
    if (l == 0) { sbias[tok] = bias_p; su[tok] = u_p; }
    __syncthreads();

    const int row = tok;
    float qrow[32];
#pragma unroll
    for (int d = 0; d < 32; d += 4) {
        float4 x = *(const float4*)(&sq[row][d]);
        qrow[d] = x.x; qrow[d + 1] = x.y; qrow[d + 2] = x.z; qrow[d + 3] = x.w;
    }
    const float urow = su[row];
    float sc[16];
    float smax = -1e30f;
#pragma unroll
    for (int jj = 0; jj < 16; jj++) {
        int j = l + (jj << 2);
        float sv2 = urow + sbias[j];
#pragma unroll
        for (int d = 0; d < 32; d += 4) {
            float4 kv = *(const float4*)(&skw[j][d]);
            sv2 += qrow[d] * kv.x + qrow[d + 1] * kv.y +
                   qrow[d + 2] * kv.z + qrow[d + 3] * kv.w;
        }
        sc[jj] = sv2;
        smax = fmaxf(smax, sv2);
    }
    smax = fmaxf(smax, __shfl_xor_sync(0xffffffffu, smax, 1));
    smax = fmaxf(smax, __shfl_xor_sync(0xffffffffu, smax, 2));
    float ssum = 0.f;
#pragma unroll
    for (int jj = 0; jj < 16; jj++) {
        sc[jj] = __expf(sc[jj] - smax);
        ssum += sc[jj];
    }
    ssum += __shfl_xor_sync(0xffffffffu, ssum, 1);
    ssum += __shfl_xor_sync(0xffffffffu, ssum, 2);
    const float inv = 1.f / ssum;
#pragma unroll
    for (int jj = 0; jj < 16; jj++) P[row][l + (jj << 2)] = sc[jj] * inv;
    __syncthreads();

    float oa0 = 0.f, oa1 = 0.f, oa2 = 0.f, oa3 = 0.f;
    float oa4 = 0.f, oa5 = 0.f, oa6 = 0.f, oa7 = 0.f;
#pragma unroll
    for (int j = 0; j < 64; j++) {
        float pv = P[row][j];
        float4 v0 = *(const float4*)(&sv[j][dl]);
        float4 v1 = *(const float4*)(&sv[j][dl + 4]);
        oa0 += pv * v0.x; oa1 += pv * v0.y; oa2 += pv * v0.z; oa3 += pv * v0.w;
        oa4 += pv * v1.x; oa5 += pv * v1.y; oa6 += pv * v1.z; oa7 += pv * v1.w;
    }
    *(float4*)(ctx + base)     = make_float4(oa0, oa1, oa2, oa3);
    *(float4*)(ctx + base + 4) = make_float4(oa4, oa5, oa6, oa7);
}

// ---------------- launch ----------------
extern "C" void kernel_launch(void* const* d_in, const int* in_sizes, int n_in,
                              void* d_out, int out_size)
{
    const float* inputs = (const float*)d_in[0];
    const float* p      = (const float*)d_in[1];
    const float* wq     = (const float*)d_in[2];
    const float* bq     = (const float*)d_in[3];
    const float* wk     = (const float*)d_in[4];
    const float* bk     = (const float*)d_in[5];
    const float* wv     = (const float*)d_in[6];
    const float* bv     = (const float*)d_in[7];
    const float* wo     = (const float*)d_in[8];
    const float* bo     = (const float*)d_in[9];
    const float* p1w    = (const float*)d_in[10];
    const float* p1b    = (const float*)d_in[11];
    const float* p2w    = (const float*)d_in[12];
    const float* p2b    = (const float*)d_in[13];
    const float* lng    = (const float*)d_in[14];
    const float* lnb    = (const float*)d_in[15];
    const float* cv     = (const float*)d_in[16];
    const float* dv     = (const float*)d_in[17];
    float* out = (float*)d_out;

    float *q, *k, *v, *pe1, *pe, *ctx;
    cudaGetSymbolAddress((void**)&q,   g_q);
    cudaGetSymbolAddress((void**)&k,   g_k);
    cudaGetSymbolAddress((void**)&v,   g_v);
    cudaGetSymbolAddress((void**)&pe1, g_pe1);
    cudaGetSymbolAddress((void**)&pe,  g_pe);
    cudaGetSymbolAddress((void**)&ctx, g_ctx);

    const dim3 gg(NTOK / BM, HID / BN, 1);
    const float qscale = 0.17677669529663689f;  // 1/sqrt(32)

    gemm_tc<<<gg, 256>>>(inputs, wq, bq, q, qscale, 0);
    gemm_tc<<<gg, 256>>>(inputs, wk, bk, k, 1.f, 0);
    gemm_tc<<<gg, 256>>>(inputs, wv, bv, v, 1.f, 0);
    pos1_k<<<NTOK / 8, 256>>>(p, p1w, p1b, lng, lnb, pe1);
    gemm_tc<<<gg, 256>>>(pe1, p2w, p2b, pe, 1.f, 1);
    attn_k<<<dim3(NWIN, NHEAD, BATCH), 256>>>(q, k, v, pe, cv, dv, ctx);
    gemm_tc<<<gg, 256>>>(ctx, wo, bo, out, 1.f, 0);
}

// round 3
// speedup vs baseline: 1.9936x; 1.5027x over previous
#include <cuda_runtime.h>
#include <cuda_bf16.h>
#include <math.h>
#include <stdint.h>

#define BATCH 4
#define SEQ   2048
#define HID   256
#define NTOK  (BATCH*SEQ)   // 8192
#define NHEAD 8
#define DPH   32
#define WINSZ 64
#define NWIN  32

// ---------------- scratch (no allocs allowed) ----------------
__device__ float g_q[NTOK*HID];
__device__ float g_k[NTOK*HID];
__device__ float g_v[NTOK*HID];
__device__ float g_pe1[NTOK*HID];
__device__ float g_pe[NTOK*HID];
__device__ float g_ctx[NTOK*HID];

__device__ __forceinline__ float gelu_exact(float x) {
    return 0.5f * x * (1.0f + erff(x * 0.70710678118654752f));
}

__device__ __forceinline__ uint32_t pkbf(float a, float b) {
    __nv_bfloat16 ha = __float2bfloat16(a);
    __nv_bfloat16 hb = __float2bfloat16(b);
    return (uint32_t)__bfloat16_as_ushort(ha) |
           ((uint32_t)__bfloat16_as_ushort(hb) << 16);
}

__device__ __forceinline__ void ldsm4(uint32_t* r, const void* p) {
    uint32_t a = (uint32_t)__cvta_generic_to_shared(p);
    asm volatile("ldmatrix.sync.aligned.m8n8.x4.shared.b16 {%0,%1,%2,%3}, [%4];"
                 : "=r"(r[0]), "=r"(r[1]), "=r"(r[2]), "=r"(r[3]) : "r"(a));
}
__device__ __forceinline__ void ldsm4t(uint32_t* r, const void* p) {
    uint32_t a = (uint32_t)__cvta_generic_to_shared(p);
    asm volatile("ldmatrix.sync.aligned.m8n8.x4.trans.shared.b16 {%0,%1,%2,%3}, [%4];"
                 : "=r"(r[0]), "=r"(r[1]), "=r"(r[2]), "=r"(r[3]) : "r"(a));
}

__device__ __forceinline__ void mma_bf16(float* d, const uint32_t* a, const uint32_t* b) {
    asm volatile(
        "mma.sync.aligned.m16n8k16.row.col.f32.bf16.bf16.f32 "
        "{%0,%1,%2,%3}, {%4,%5,%6,%7}, {%8,%9}, {%0,%1,%2,%3};\n"
        : "+f"(d[0]), "+f"(d[1]), "+f"(d[2]), "+f"(d[3])
        : "r"(a[0]), "r"(a[1]), "r"(a[2]), "r"(a[3]), "r"(b[0]), "r"(b[1]));
}

// ---------------- tensor-core GEMM: C = act(scale*(A@W + bias)) ----------------
// A: (8192,256) rm, W: (256,256) rm. 3xBF16 compensated split (hh + hl + lh).
// BM=128, BN=64, BK=32. 8 warps; warp tile 32x32 (2 x m16, 4 x n8).
#define BM 128
#define BN 64
#define BKG 32

__global__ __launch_bounds__(256) void gemm_tc(
    const float* __restrict__ A, const float* __restrict__ W,
    const float* __restrict__ bias, float* __restrict__ C,
    float scale, int act)
{
    __shared__ __nv_bfloat16 Ah[BM][40];   // stride 80B: LDSM-phase conflict-free
    __shared__ __nv_bfloat16 Al[BM][40];
    __shared__ __nv_bfloat16 Bh[BKG][72];  // stride 144B: conflict-free
    __shared__ __nv_bfloat16 Bl[BKG][72];

    const int tid  = threadIdx.x;
    const int wid  = tid >> 5;
    const int lane = tid & 31;
    const int g = lane >> 2;
    const int q = lane & 3;
    const int wm = (wid & 3) * 32;
    const int wn = (wid >> 2) * 32;
    const int m0 = blockIdx.x * BM;
    const int n0 = blockIdx.y * BN;

    float acc[2][4][4];
#pragma unroll
    for (int mt = 0; mt < 2; mt++)
#pragma unroll
        for (int nt = 0; nt < 4; nt++)
#pragma unroll
            for (int i = 0; i < 4; i++) acc[mt][nt][i] = 0.f;

    // staging registers (software pipeline)
    float4 ar[4], br[2];
    const int arow[1] = {0};
    (void)arow;

#define LOADG(KK)                                                              \
    {                                                                          \
        _Pragma("unroll")                                                      \
        for (int i = 0; i < 4; i++) {                                          \
            int f = i * 256 + tid;                                             \
            int row = f >> 3, c4 = (f & 7) << 2;                               \
            ar[i] = *(const float4*)(A + (size_t)(m0 + row) * 256 + (KK) + c4);\
        }                                                                      \
        _Pragma("unroll")                                                      \
        for (int i = 0; i < 2; i++) {                                          \
            int f = i * 256 + tid;                                             \
            int row = f >> 4, c4 = (f & 15) << 2;                              \
            br[i] = *(const float4*)(W + (size_t)((KK) + row) * 256 + n0 + c4);\
        }                                                                      \
    }

#define STAGE()                                                                \
    {                                                                          \
        _Pragma("unroll")                                                      \
        for (int i = 0; i < 4; i++) {                                          \
            int f = i * 256 + tid;                                             \
            int row = f >> 3, c4 = (f & 7) << 2;                               \
            float4 v = ar[i];                                                  \
            uint32_t h01 = pkbf(v.x, v.y), h23 = pkbf(v.z, v.w);               \
            float hx = __bfloat162float(__ushort_as_bfloat16((ushort)h01));    \
            float hy = __bfloat162float(__ushort_as_bfloat16((ushort)(h01>>16)));\
            float hz = __bfloat162float(__ushort_as_bfloat16((ushort)h23));    \
            float hw = __bfloat162float(__ushort_as_bfloat16((ushort)(h23>>16)));\
            *(uint32_t*)(&Ah[row][c4])     = h01;                              \
            *(uint32_t*)(&Ah[row][c4 + 2]) = h23;                              \
            *(uint32_t*)(&Al[row][c4])     = pkbf(v.x - hx, v.y - hy);         \
            *(uint32_t*)(&Al[row][c4 + 2]) = pkbf(v.z - hz, v.w - hw);         \
        }                                                                      \
        _Pragma("unroll")                                                      \
        for (int i = 0; i < 2; i++) {                                          \
            int f = i * 256 + tid;                                             \
            int row = f >> 4, c4 = (f & 15) << 2;                              \
            float4 v = br[i];                                                  \
            uint32_t h01 = pkbf(v.x, v.y), h23 = pkbf(v.z, v.w);               \
            float hx = __bfloat162float(__ushort_as_bfloat16((ushort)h01));    \
            float hy = __bfloat162float(__ushort_as_bfloat16((ushort)(h01>>16)));\
            float hz = __bfloat162float(__ushort_as_bfloat16((ushort)h23));    \
            float hw = __bfloat162float(__ushort_as_bfloat16((ushort)(h23>>16)));\
            *(uint32_t*)(&Bh[row][c4])     = h01;                              \
            *(uint32_t*)(&Bh[row][c4 + 2]) = h23;                              \
            *(uint32_t*)(&Bl[row][c4])     = pkbf(v.x - hx, v.y - hy);         \
            *(uint32_t*)(&Bl[row][c4 + 2]) = pkbf(v.z - hz, v.w - hw);         \
        }                                                                      \
    }

    LOADG(0);
    for (int kk = 0; kk < 256; kk += BKG) {
        STAGE();
        __syncthreads();
        if (kk + BKG < 256) LOADG(kk + BKG);

        const int la = lane & 15;
        const int lo8 = (lane >> 4) << 3;
#pragma unroll
        for (int ks = 0; ks < BKG; ks += 16) {
            uint32_t ah[2][4], al[2][4], bh[2][4], bl[2][4];
#pragma unroll
            for (int mt = 0; mt < 2; mt++) {
                ldsm4(ah[mt], &Ah[wm + mt * 16 + la][ks + lo8]);
                ldsm4(al[mt], &Al[wm + mt * 16 + la][ks + lo8]);
            }
#pragma unroll
            for (int np = 0; np < 2; np++) {
                ldsm4t(bh[np], &Bh[ks + la][wn + np * 16 + lo8]);
                ldsm4t(bl[np], &Bl[ks + la][wn + np * 16 + lo8]);
            }
#pragma unroll
            for (int mt = 0; mt < 2; mt++)
#pragma unroll
                for (int nt = 0; nt < 4; nt++) {
                    const uint32_t* ph = &bh[nt >> 1][(nt & 1) * 2];
                    const uint32_t* pl = &bl[nt >> 1][(nt & 1) * 2];
                    mma_bf16(acc[mt][nt], ah[mt], ph);
                    mma_bf16(acc[mt][nt], ah[mt], pl);
                    mma_bf16(acc[mt][nt], al[mt], ph);
                }
        }
        __syncthreads();
    }

    // ---- epilogue ----
#pragma unroll
    for (int mt = 0; mt < 2; mt++) {
        int r0 = m0 + wm + mt * 16 + g;
#pragma unroll
        for (int nt = 0; nt < 4; nt++) {
            int cn = n0 + wn + nt * 8 + 2 * q;
            float2 b2 = *(const float2*)(bias + cn);
            float v0 = (acc[mt][nt][0] + b2.x) * scale;
            float v1 = (acc[mt][nt][1] + b2.y) * scale;
            float v2 = (acc[mt][nt][2] + b2.x) * scale;
            float v3 = (acc[mt][nt][3] + b2.y) * scale;
            if (act) {
                v0 = gelu_exact(v0); v1 = gelu_exact(v1);
                v2 = gelu_exact(v2); v3 = gelu_exact(v3);
            }
            *(float2*)(C + (size_t)r0 * 256 + cn)       = make_float2(v0, v1);
            *(float2*)(C + (size_t)(r0 + 8) * 256 + cn) = make_float2(v2, v3);
        }
    }
}

// ---------------- pos-MLP stage 1: weights in smem, 32 tokens/block ----------------
__global__ __launch_bounds__(256) void pos1_k(
    const float* __restrict__ p, const float* __restrict__ p1w,
    const float* __restrict__ p1b, const float* __restrict__ lng,
    const float* __restrict__ lnb, float* __restrict__ out)
{
    __shared__ float w0[256], w1[256], b1[256], gw[256], bw[256];
    const int tid = threadIdx.x;
    w0[tid] = p1w[tid];
    w1[tid] = p1w[256 + tid];
    b1[tid] = p1b[tid];
    gw[tid] = lng[tid];
    bw[tid] = lnb[tid];
    __syncthreads();

    const int warp = tid >> 5;
    const int lane = tid & 31;
#pragma unroll
    for (int tt = 0; tt < 4; tt++) {
        const int tok = blockIdx.x * 32 + warp * 4 + tt;
        const float p0  = p[tok * 2 + 0];
        const float p1v = p[tok * 2 + 1];

        float h[8];
        float s = 0.f;
#pragma unroll
        for (int j = 0; j < 8; j++) {
            int n = lane + 32 * j;
            h[j] = p0 * w0[n] + p1v * w1[n] + b1[n];
            s += h[j];
        }
#pragma unroll
        for (int o = 16; o; o >>= 1) s += __shfl_xor_sync(0xffffffffu, s, o);
        const float mu = s * (1.f / 256.f);

        float vs = 0.f;
#pragma unroll
        for (int j = 0; j < 8; j++) {
            float d = h[j] - mu;
            vs += d * d;
        }
#pragma unroll
        for (int o = 16; o; o >>= 1) vs += __shfl_xor_sync(0xffffffffu, vs, o);
        const float rstd = rsqrtf(vs * (1.f / 256.f) + 1e-6f);

#pragma unroll
        for (int j = 0; j < 8; j++) {
            int n = lane + 32 * j;
            float y = (h[j] - mu) * rstd * gw[n] + bw[n];
            out[(size_t)tok * 256 + n] = gelu_exact(y);
        }
    }
}

// ---------------- windowed attention ----------------
// S[i,j] = q_i·(k_j - pe_j) + (c·k_j - d·pe_j) + (q_i + d)·pe_i
__global__ __launch_bounds__(256) void attn_k(
    const float* __restrict__ q, const float* __restrict__ k,
    const float* __restrict__ v, const float* __restrict__ pe,
    const float* __restrict__ cvec, const float* __restrict__ dvec,
    float* __restrict__ ctx)
{
    const int w = blockIdx.x, h = blockIdx.y, b = blockIdx.z;

    __shared__ float sq[64][36];
    __shared__ float skw[64][36];
    __shared__ float sv[64][36];
    __shared__ float sbias[64];
    __shared__ float su[64];
    __shared__ float P[64][65];

    const int t = threadIdx.x;
    const int tok = t >> 2;
    const int l = t & 3;
    const int dl = l * 8;

    const int s = w * 64 + tok;
    const int o = s >> 4, r = s & 15;
    const int ic = ((o & 63) << 1) + (o >> 6);
    const int orig = ic * 16 + r;
    const size_t base = ((size_t)(b * SEQ + orig)) * 256 + h * 32 + dl;

    const float* cp = cvec + h * 32 + dl;
    const float* dp = dvec + h * 32 + dl;

    float bias_p = 0.f, u_p = 0.f;
#pragma unroll
    for (int i = 0; i < 8; i += 4) {
        float4 xq = *(const float4*)(q + base + i);
        float4 xk = *(const float4*)(k + base + i);
        float4 xv = *(const float4*)(v + base + i);
        float4 xp = *(const float4*)(pe + base + i);
        float4 xc = *(const float4*)(cp + i);
        float4 xd = *(const float4*)(dp + i);
        *(float4*)(&sq[tok][dl + i]) = xq;
        *(float4*)(&sv[tok][dl + i]) = xv;
        float4 kw = make_float4(xk.x - xp.x, xk.y - xp.y, xk.z - xp.z, xk.w - xp.w);
        *(float4*)(&skw[tok][dl + i]) = kw;
        bias_p += xc.x * xk.x + xc.y * xk.y + xc.z * xk.z + xc.w * xk.w;
        bias_p -= xd.x * xp.x + xd.y * xp.y + xd.z * xp.z + xd.w * xp.w;
        u_p += (xq.x + xd.x) * xp.x + (xq.y + xd.y) * xp.y +
               (xq.z + xd.z) * xp.z + (xq.w + xd.w) * xp.w;
    }
    bias_p += __shfl_xor_sync(0xffffffffu, bias_p, 1);
    bias_p += __shfl_xor_sync(0xffffffffu, bias_p, 2);
    u_p += __shfl_xor_sync(0xffffffffu, u_p, 1);
    u_p += __shfl_xor_sync(0xffffffffu, u_p, 2);
    if (l == 0) { sbias[tok] = bias_p; su[tok] = u_p; }
    __syncthreads();

    const int row = tok;
    float qrow[32];
#pragma unroll
    for (int d = 0; d < 32; d += 4) {
        float4 x = *(const float4*)(&sq[row][d]);
        qrow[d] = x.x; qrow[d + 1] = x.y; qrow[d + 2] = x.z; qrow[d + 3] = x.w;
    }
    const float urow = su[row];
    float sc[16];
    float smax = -1e30f;
#pragma unroll
    for (int jj = 0; jj < 16; jj++) {
        int j = l + (jj << 2);
        float sv2 = urow + sbias[j];
#pragma unroll
        for (int d = 0; d < 32; d += 4) {
            float4 kv = *(const float4*)(&skw[j][d]);
            sv2 += qrow[d] * kv.x + qrow[d + 1] * kv.y +
                   qrow[d + 2] * kv.z + qrow[d + 3] * kv.w;
        }
        sc[jj] = sv2;
        smax = fmaxf(smax, sv2);
    }
    smax = fmaxf(smax, __shfl_xor_sync(0xffffffffu, smax, 1));
    smax = fmaxf(smax, __shfl_xor_sync(0xffffffffu, smax, 2));
    float ssum = 0.f;
#pragma unroll
    for (int jj = 0; jj < 16; jj++) {
        sc[jj] = __expf(sc[jj] - smax);
        ssum += sc[jj];
    }
    ssum += __shfl_xor_sync(0xffffffffu, ssum, 1);
    ssum += __shfl_xor_sync(0xffffffffu, ssum, 2);
    const float inv = 1.f / ssum;
#pragma unroll
    for (int jj = 0; jj < 16; jj++) P[row][l + (jj << 2)] = sc[jj] * inv;
    __syncthreads();

    float oa0 = 0.f, oa1 = 0.f, oa2 = 0.f, oa3 = 0.f;
    float oa4 = 0.f, oa5 = 0.f, oa6 = 0.f, oa7 = 0.f;
#pragma unroll
    for (int j = 0; j < 64; j++) {
        float pv = P[row][j];
        float4 v0 = *(const float4*)(&sv[j][dl]);
        float4 v1 = *(const float4*)(&sv[j][dl + 4]);
        oa0 += pv * v0.x; oa1 += pv * v0.y; oa2 += pv * v0.z; oa3 += pv * v0.w;
        oa4 += pv * v1.x; oa5 += pv * v1.y; oa6 += pv * v1.z; oa7 += pv * v1.w;
    }
    *(float4*)(ctx + base)     = make_float4(oa0, oa1, oa2, oa3);
    *(float4*)(ctx + base + 4) = make_float4(oa4, oa5, oa6, oa7);
}

// ---------------- launch ----------------
extern "C" void kernel_launch(void* const* d_in, const int* in_sizes, int n_in,
                              void* d_out, int out_size)
{
    const float* inputs = (const float*)d_in[0];
    const float* p      = (const float*)d_in[1];
    const float* wq     = (const float*)d_in[2];
    const float* bq     = (const float*)d_in[3];
    const float* wk     = (const float*)d_in[4];
    const float* bk     = (const float*)d_in[5];
    const float* wv     = (const float*)d_in[6];
    const float* bv     = (const float*)d_in[7];
    const float* wo     = (const float*)d_in[8];
    const float* bo     = (const float*)d_in[9];
    const float* p1w    = (const float*)d_in[10];
    const float* p1b    = (const float*)d_in[11];
    const float* p2w    = (const float*)d_in[12];
    const float* p2b    = (const float*)d_in[13];
    const float* lng    = (const float*)d_in[14];
    const float* lnb    = (const float*)d_in[15];
    const float* cv     = (const float*)d_in[16];
    const float* dv     = (const float*)d_in[17];
    float* out = (float*)d_out;

    float *q, *k, *v, *pe1, *pe, *ctx;
    cudaGetSymbolAddress((void**)&q,   g_q);
    cudaGetSymbolAddress((void**)&k,   g_k);
    cudaGetSymbolAddress((void**)&v,   g_v);
    cudaGetSymbolAddress((void**)&pe1, g_pe1);
    cudaGetSymbolAddress((void**)&pe,  g_pe);
    cudaGetSymbolAddress((void**)&ctx, g_ctx);

    const dim3 gg(NTOK / BM, HID / BN, 1);
    const float qscale = 0.17677669529663689f;  // 1/sqrt(32)

    gemm_tc<<<gg, 256>>>(inputs, wq, bq, q, qscale, 0);
    gemm_tc<<<gg, 256>>>(inputs, wk, bk, k, 1.f, 0);
    gemm_tc<<<gg, 256>>>(inputs, wv, bv, v, 1.f, 0);
    pos1_k<<<NTOK / 32, 256>>>(p, p1w, p1b, lng, lnb, pe1);
    gemm_tc<<<gg, 256>>>(pe1, p2w, p2b, pe, 1.f, 1);
    attn_k<<<dim3(NWIN, NHEAD, BATCH), 256>>>(q, k, v, pe, cv, dv, ctx);
    gemm_tc<<<gg, 256>>>(ctx, wo, bo, out, 1.f, 0);
}